// round 15
// baseline (speedup 1.0000x reference)
#include <cuda_runtime.h>
#include <stdint.h>

typedef unsigned long long u64;
typedef unsigned int u32;

#define NLEV 5
#define CLSN 16
#define TOPK 1000
#define NTOT 785664
#define HBITS 13
#define HB (1 << HBITS)        /* 8192 bins: ord >> 19 */
#define WCAP 4096
#define CHUNK 1536
#define NCHUNK 512             /* 512*1536 = 786432 >= NTOT */
#define MAXD 4.135166556742356f

__device__ __constant__ int d_off[6] = {0, 589824, 737280, 774144, 783360, 785664};
__device__ __constant__ int d_len[5] = {589824, 147456, 36864, 9216, 2304};

struct Ptrs {
    const float* anc[NLEV];
    const float* cls[NLEV];
    const float* reg[NLEV];
};

// ------- scratch (device globals; zero-initialized at load). g_hist is
// re-zeroed by k_rank_emit (which runs after k_resolve consumed it); g_nwin
// is zeroed by k_resolve (before k_select produces into it) — so every
// call, including graph replays, sees the required entry state. -------
__device__ int g_hist[NLEV * HB];
__device__ int g_nwin[NLEV];
__device__ u32 g_ord[NTOT];
__device__ u64 g_win[NLEV][WCAP];
__device__ int g_thr[NLEV];

__device__ __forceinline__ int level_of(int a) {
    int l = 0;
#pragma unroll
    for (int j = 1; j < NLEV; j++) l += (a >= d_off[j]);
    return l;
}

// ---- K1: ruler (max of 16 logits) + PRIVATE shared 13-bit histogram ----
__global__ void __launch_bounds__(512)
k_ruler(Ptrs p) {
    __shared__ u32 h[HB];                     // 32 KB
    const int t = threadIdx.x;
    for (int b = t; b < HB; b += 512) h[b] = 0;
    __syncthreads();

    const int cstart = blockIdx.x * CHUNK;
    const int l = level_of(cstart);
    const int base = d_off[l];
    const int iend = (cstart + CHUNK < NTOT) ? cstart + CHUNK : NTOT;
    const float4* cls4 = (const float4*)p.cls[l];

#pragma unroll
    for (int q = 0; q < 3; q++) {
        int a = cstart + q * 512 + t;
        if (a < iend) {
            int i = a - base;
            float4 va = cls4[i * 4 + 0], vb = cls4[i * 4 + 1];
            float4 vc = cls4[i * 4 + 2], vd = cls4[i * 4 + 3];
            float m = fmaxf(fmaxf(fmaxf(va.x, va.y), fmaxf(va.z, va.w)),
                            fmaxf(fmaxf(vb.x, vb.y), fmaxf(vb.z, vb.w)));
            m = fmaxf(m, fmaxf(fmaxf(vc.x, vc.y), fmaxf(vc.z, vc.w)));
            m = fmaxf(m, fmaxf(fmaxf(vd.x, vd.y), fmaxf(vd.z, vd.w)));
            u32 u = __float_as_uint(m);
            u32 ord = (u & 0x80000000u) ? ~u : (u | 0x80000000u);  // monotonic
            g_ord[a] = ord;
            atomicAdd(&h[ord >> (32 - HBITS)], 1u);
        }
    }
    __syncthreads();

    int* gh = &g_hist[l * HB];
    for (int b = t; b < HB; b += 512) {
        u32 c = h[b];
        if (c) atomicAdd(&gh[b], (int)c);     // <=384 adds per address
    }
}

// ---- K2: per-level threshold bin + zero g_nwin ----
__global__ void k_resolve() {
    const int l = blockIdx.x;
    const int t = threadIdx.x;                // 256 threads
    const int CH = HB / 256;                  // 32 bins/thread
    __shared__ int csum[256];
    __shared__ int s_cidx, s_sufnext;
    const int* h = &g_hist[l * HB];

    if (t == 0) g_nwin[l] = 0;                // consumed only by k_select (later)

    int base = t * CH, s = 0;
#pragma unroll 4
    for (int j = 0; j < CH; j++) s += h[base + j];
    csum[t] = s;
    __syncthreads();
    for (int off = 1; off < 256; off <<= 1) { // reversed scan -> suffix sums
        int v = csum[t];
        int add = (t + off < 256) ? csum[t + off] : 0;
        __syncthreads();
        csum[t] = v + add;
        __syncthreads();
    }
    if (csum[t] >= TOPK && (t == 255 || csum[t + 1] < TOPK)) {
        s_cidx = t;
        s_sufnext = (t == 255) ? 0 : csum[t + 1];
    }
    __syncthreads();
    if (t == 0) {
        int cbase = s_cidx * CH;
        int suf = s_sufnext, b = cbase + CH - 1;
        for (int j = CH - 1; j >= 0; j--) {
            suf += h[cbase + j];
            b = cbase + j;
            if (suf >= TOPK) break;
        }
        g_thr[l] = b;
    }
}

// ---- K3: collect keys with top13 >= threshold (ballot-aggregated) ----
__global__ void __launch_bounds__(512)
k_select() {
    const int t = threadIdx.x;
    const int cstart = blockIdx.x * CHUNK;
    const int l = level_of(cstart);
    const int base = d_off[l];
    const int iend = (cstart + CHUNK < NTOT) ? cstart + CHUNK : NTOT;
    const u32 thr = (u32)g_thr[l];
    const int lane = t & 31;

#pragma unroll
    for (int q = 0; q < 3; q++) {
        int a = cstart + q * 512 + t;
        bool win = false;
        u32 ord = 0;
        if (a < iend) {
            ord = g_ord[a];
            win = (ord >> (32 - HBITS)) >= thr;
        }
        unsigned act = __activemask();
        unsigned mask = __ballot_sync(act, win);
        if (win) {
            int leader = __ffs(mask) - 1;
            int rk = __popc(mask & ((1u << lane) - 1));
            int wbase = 0;
            if (lane == leader) wbase = atomicAdd(&g_nwin[l], __popc(mask));
            wbase = __shfl_sync(mask, wbase, leader);
            int w = wbase + rk;
            if (w < WCAP) g_win[l][w] = ((u64)ord << 32) | (u32)(a - base);
        }
    }
}

// ---- K4: warp-per-element exact rank + DIRECT emit; also zeroes g_hist.
// grid (WCAP/8, NLEV), block 256 = 8 warps, ONE element per warp.
// rank(e) = #{keys < e} over unique keys (~ord, idx) == exact jax top_k
// position. The warp then decodes the box once and lanes 0..15 write the
// 16 output rows (coalesced cls read, contiguous stores). No g_sel trip.
__global__ void __launch_bounds__(256)
k_rank_emit(Ptrs p, float* __restrict__ out) {
    __shared__ u64 s[WCAP];       // 32 KB worst case; typical n ~1250
    const int l = blockIdx.y;
    const int t = threadIdx.x;
    const int warp = t >> 5;
    const int lane = t & 31;

    // cleanup for next call (spread over all blocks; mostly the idle ones)
    {
        int g = (blockIdx.y * gridDim.x + blockIdx.x) * 256 + t;
        if (g < NLEV * HB) g_hist[g] = 0;
    }

    int n = g_nwin[l];
    if (n > WCAP) n = WCAP;
    if (blockIdx.x * 8 >= n) return;          // whole block out of range

    const u64* win = g_win[l];
    for (int i = t; i < n; i += 256)
        s[i] = win[i] ^ 0xFFFFFFFF00000000ULL;   // ascending (~ord, idx)
    __syncthreads();

    const int e = blockIdx.x * 8 + warp;
    if (e >= n) return;
    const u64 me = s[e];
    int cnt = 0;
    for (int j = lane; j < n; j += 32)        // conflict-free strided LDS
        cnt += (s[j] < me);
    const int rank = __reduce_add_sync(0xFFFFFFFFu, cnt);   // all lanes get it
    if (rank >= TOPK) return;

    u32 idx = (u32)(me & 0xFFFFFFFFu);
    if (idx >= (u32)d_len[l]) idx = 0;        // safety (never hit on valid data)

    // decode box once per warp (broadcast loads: all lanes same address)
    float4 a4 = ((const float4*)p.anc[l])[idx];
    float4 r4 = ((const float4*)p.reg[l])[idx * 2];
    float w = a4.z - a4.x, h = a4.w - a4.y;
    float cx = a4.x + 0.5f * w, cy = a4.y + 0.5f * h;
    float pcx = cx + r4.x * w, pcy = cy + r4.y * h;
    float pw = w * expf(fminf(r4.z, MAXD));
    float ph = h * expf(fminf(r4.w, MAXD));
    float x0 = pcx - 0.5f * pw, y0 = pcy - 0.5f * ph;
    float x1 = pcx + 0.5f * pw, y1 = pcy + 0.5f * ph;

    if (lane < CLSN) {
        float score = p.cls[l][(size_t)idx * CLSN + lane];  // coalesced 64B
        float sg = 1.0f / (1.0f + expf(-score));
        float* lout = out + (size_t)l * TOPK * CLSN * 6;
        float2* o2 = (float2*)(lout + ((size_t)rank * CLSN + lane) * 6);
        o2[0] = make_float2(x0, y0);
        o2[1] = make_float2(x1, y1);
        o2[2] = make_float2(sg, (float)(lane + 1));
    }
}

extern "C" void kernel_launch(void* const* d_in, const int* in_sizes, int n_in,
                              void* d_out, int out_size) {
    (void)in_sizes; (void)n_in; (void)out_size;
    Ptrs p;
    for (int l = 0; l < NLEV; l++) {
        p.anc[l] = (const float*)d_in[3 * l + 0];
        p.cls[l] = (const float*)d_in[3 * l + 1];
        p.reg[l] = (const float*)d_in[3 * l + 2];
    }

    k_ruler<<<NCHUNK, 512>>>(p);
    k_resolve<<<NLEV, 256>>>();
    k_select<<<NCHUNK, 512>>>();
    dim3 gr(WCAP / 8, NLEV);
    k_rank_emit<<<gr, 256>>>(p, (float*)d_out);
}